// round 2
// baseline (speedup 1.0000x reference)
#include <cuda_runtime.h>
#include <cuda_bf16.h>
#include <cstdint>

#define DINL __device__ __forceinline__

// ---------------- problem constants ----------------
constexpr int   BHALF = 4096;
constexpr int   NTOT  = 8192;           // 2B rows
constexpr int   DDIM  = 256;            // K
constexpr int   TILE  = 128;            // M = N tile
constexpr int   RBLK  = NTOT / TILE;    // 64 row blocks
constexpr int   NT_TOT = RBLK * RBLK;   // 4096 tiles
constexpr int   GRID  = 296;            // 2 exact waves of 148 SMs
// alpha = sqrt(log2(e)/T): (a u_i)·(a u_j) = s·log2(e)/T = y, so exp(s/T)=2^y
constexpr float ALPHA = 1.6986436f;
constexpr float LN2F  = 0.693147180559945f;

// SMEM: A tile 128x256 bf16 (64KB) + two B buffers (64KB each)
constexpr int SM_A  = 0;
constexpr int SM_B0 = 65536;
constexpr int SM_B1 = 131072;
constexpr int SMEM_BYTES = 196608;

// ---------------- device scratch (no allocation allowed) --------------------
__device__ __align__(16) __nv_bfloat16 g_z[NTOT * DDIM];   // 4 MB
__device__ float g_partial[NTOT];
__device__ float g_pos[NTOT];

// ---------------- PTX helpers ----------------
DINL uint32_t smem_u32(const void* p) {
    uint32_t a;
    asm("{ .reg .u64 t; cvta.to.shared.u64 t, %1; cvt.u32.u64 %0, t; }"
        : "=r"(a) : "l"(p));
    return a;
}
DINL float ex2f(float x) { float r; asm("ex2.approx.f32 %0, %1;" : "=f"(r) : "f"(x)); return r; }
DINL float lg2f(float x) { float r; asm("lg2.approx.f32 %0, %1;" : "=f"(r) : "f"(x)); return r; }

DINL void cp_commit() { asm volatile("cp.async.commit_group;" ::: "memory"); }
DINL void cp_wait0()  { asm volatile("cp.async.wait_group 0;" ::: "memory"); }
DINL void cp_wait1()  { asm volatile("cp.async.wait_group 1;" ::: "memory"); }

DINL void ldsm4(uint32_t& d0, uint32_t& d1, uint32_t& d2, uint32_t& d3, uint32_t addr) {
    asm volatile("ldmatrix.sync.aligned.m8n8.x4.shared.b16 {%0,%1,%2,%3}, [%4];"
                 : "=r"(d0), "=r"(d1), "=r"(d2), "=r"(d3) : "r"(addr));
}
DINL void mma16816(float* c, uint32_t a0, uint32_t a1, uint32_t a2, uint32_t a3,
                   uint32_t b0, uint32_t b1) {
    asm volatile("mma.sync.aligned.m16n8k16.row.col.f32.bf16.bf16.f32 "
                 "{%0,%1,%2,%3}, {%4,%5,%6,%7}, {%8,%9}, {%0,%1,%2,%3};"
                 : "+f"(c[0]), "+f"(c[1]), "+f"(c[2]), "+f"(c[3])
                 : "r"(a0), "r"(a1), "r"(a2), "r"(a3), "r"(b0), "r"(b1));
}

// Load one 128x256 bf16 tile of g_z into SMEM, XOR-swizzled (16B chunk index
// within 512B row XORed with row&7 -> conflict-free ldmatrix).
DINL void load_tile(uint32_t dst, int row0) {
    const char* src = reinterpret_cast<const char*>(g_z) + (size_t)row0 * 512;
    const int t = threadIdx.x;
    #pragma unroll
    for (int it = 0; it < 16; ++it) {
        int lin = it * 256 + t;
        int row = lin >> 5;
        int ch  = lin & 31;
        uint32_t sw = (uint32_t)row * 512u + (uint32_t)((ch ^ (row & 7)) << 4);
        const void* gp = src + (size_t)row * 512 + (size_t)ch * 16;
        asm volatile("cp.async.cg.shared.global [%0], [%1], 16;"
                     :: "r"(dst + sw), "l"(gp) : "memory");
    }
}

// ---------------- fused per-tile compute: 128x128 mma + exp2 + row-sum ------
DINL void compute_tile(uint32_t a_base, uint32_t b_base, int w, int lane,
                       bool diag, bool pos, int rb, float& ra0, float& ra1) {
    const int mi = lane >> 3, li = lane & 7;
    // A fragment addressing (rows w*16 .. w*16+15)
    const int rA = w * 16 + ((mi & 1) << 3) + li;
    const uint32_t aRow = a_base + (uint32_t)rA * 512u;
    const int axr = rA & 7, acp = mi >> 1;
    // B fragment addressing
    const int rBo = ((mi >> 1) << 3) + li;
    const int bcp = mi & 1;

    float acc[16][4];
    #pragma unroll
    for (int j = 0; j < 16; ++j) {
        acc[j][0] = 0.f; acc[j][1] = 0.f; acc[j][2] = 0.f; acc[j][3] = 0.f;
    }

    #pragma unroll 4
    for (int s = 0; s < 16; ++s) {
        uint32_t a0, a1, a2, a3;
        ldsm4(a0, a1, a2, a3, aRow + (uint32_t)(((s * 2 + acp) ^ axr) << 4));
        #pragma unroll
        for (int jp = 0; jp < 8; ++jp) {
            int r = jp * 16 + rBo;
            uint32_t b0, b1, b2, b3;
            ldsm4(b0, b1, b2, b3,
                  b_base + (uint32_t)r * 512u +
                  (uint32_t)(((s * 2 + bcp) ^ (r & 7)) << 4));
            mma16816(acc[2 * jp],     a0, a1, a2, a3, b0, b1);
            mma16816(acc[2 * jp + 1], a0, a1, a2, a3, b2, b3);
        }
    }

    // epilogue: exp2 + masked row accumulation
    const int baseRow = w * 16 + (lane >> 2);   // thread rows: baseRow, baseRow+8
    const int baseCol = (lane & 3) * 2;
    float e0 = 0.f, e1 = 0.f;
    if (diag | pos) {
        #pragma unroll
        for (int j = 0; j < 16; ++j) {
            #pragma unroll
            for (int q = 0; q < 4; ++q) {
                float y = acc[j][q];
                int rl = baseRow + ((q & 2) << 2);
                int cl = j * 8 + baseCol + (q & 1);
                float e = ex2f(y);
                if (diag && rl == cl) e = 0.f;                 // mask self-sim
                if (pos  && rl == cl) g_pos[rb * 128 + rl] = y; // positive logit
                if (q & 2) e1 += e; else e0 += e;
            }
        }
    } else {
        #pragma unroll
        for (int j = 0; j < 16; ++j) {
            e0 += ex2f(acc[j][0]) + ex2f(acc[j][1]);
            e1 += ex2f(acc[j][2]) + ex2f(acc[j][3]);
        }
    }
    ra0 += e0; ra1 += e1;
}

DINL void flush_rows(int rb, int w, int lane, float& a0, float& a1) {
    float v0 = a0, v1 = a1;
    v0 += __shfl_xor_sync(0xffffffffu, v0, 1);
    v0 += __shfl_xor_sync(0xffffffffu, v0, 2);
    v1 += __shfl_xor_sync(0xffffffffu, v1, 1);
    v1 += __shfl_xor_sync(0xffffffffu, v1, 2);
    if ((lane & 3) == 0) {
        int r = rb * 128 + w * 16 + (lane >> 2);
        atomicAdd(&g_partial[r],     v0);
        atomicAdd(&g_partial[r + 8], v1);
    }
    a0 = 0.f; a1 = 0.f;
}

// ---------------- kernel 1: normalize + pre-scale + bf16 cast ----------------
__global__ void prep_kernel(const float* __restrict__ xi, const float* __restrict__ xj) {
    const int row = blockIdx.x;
    const int tid = threadIdx.x;
    const float* x = (row < BHALF) ? (xi + (size_t)row * DDIM)
                                   : (xj + (size_t)(row - BHALF) * DDIM);
    float v = x[tid];
    float s = v * v;
    #pragma unroll
    for (int o = 16; o; o >>= 1) s += __shfl_xor_sync(0xffffffffu, s, o);
    __shared__ float ws[8];
    if ((tid & 31) == 0) ws[tid >> 5] = s;
    __syncthreads();
    float tot = ws[0] + ws[1] + ws[2] + ws[3] + ws[4] + ws[5] + ws[6] + ws[7];
    float scale = ALPHA / fmaxf(sqrtf(tot), 1e-12f);
    g_z[(size_t)row * DDIM + tid] = __float2bfloat16(v * scale);
    if (tid == 0) g_partial[row] = 0.f;   // zero accumulators every launch
}

// ---------------- kernel 2: persistent fused GEMM ---------------------------
__global__ void __launch_bounds__(256, 1) gemm_kernel() {
    extern __shared__ char smem[];
    const uint32_t sb = smem_u32(smem);
    const uint32_t A  = sb + SM_A;
    const uint32_t B0 = sb + SM_B0;
    const uint32_t B1 = sb + SM_B1;
    const int tid = threadIdx.x, w = tid >> 5, lane = tid & 31;

    // contiguous tile range per CTA: 4096 = 296*13 + 248
    const int c = blockIdx.x;
    const int start = c * 13 + min(c, 248);
    const int count = 13 + (c < 248 ? 1 : 0);

    load_tile(A,  (start >> 6) * 128);
    load_tile(B0, (start & 63) * 128);
    cp_commit();
    cp_wait0();
    __syncthreads();

    float ra0 = 0.f, ra1 = 0.f;
    int buf = 0;

    for (int i = 0; i < count; ++i) {
        const int t = start + i;
        const int trb = t >> 6, tct = t & 63;
        const bool haveNext = (i + 1 < count);
        const bool nextSame = haveNext && (((t + 1) >> 6) == trb);

        if (nextSame) {               // prefetch next B tile into other buffer
            load_tile(buf ? B0 : B1, ((t + 1) & 63) * 128);
            cp_commit();
            cp_wait1();
        } else {
            cp_wait0();
        }
        __syncthreads();

        compute_tile(A, buf ? B1 : B0, w, lane,
                     tct == trb, tct == (trb ^ 32), trb, ra0, ra1);
        __syncthreads();

        if (!nextSame) {
            flush_rows(trb, w, lane, ra0, ra1);
            if (haveNext) {           // row-block change: reload A + next B
                load_tile(A, ((t + 1) >> 6) * 128);
                load_tile(buf ? B0 : B1, ((t + 1) & 63) * 128);
                cp_commit();
            }
        }
        buf ^= 1;
    }
}

// ---------------- kernel 3: per-row log + positive term + mean ---------------
__global__ void final_kernel(float* __restrict__ out) {
    float local = 0.f;
    for (int r = threadIdx.x; r < NTOT; r += 256) {
        // loss_r = ln(denom) - s_pos/T = ln2 * (log2(denom) - y_pos)
        local += lg2f(g_partial[r]) - g_pos[r];
    }
    #pragma unroll
    for (int o = 16; o; o >>= 1) local += __shfl_xor_sync(0xffffffffu, local, o);
    __shared__ float ws[8];
    if ((threadIdx.x & 31) == 0) ws[threadIdx.x >> 5] = local;
    __syncthreads();
    if (threadIdx.x == 0) {
        float t = 0.f;
        #pragma unroll
        for (int i = 0; i < 8; ++i) t += ws[i];
        out[0] = t * (LN2F / (float)NTOT);
    }
}

// ---------------- entry point ----------------
extern "C" void kernel_launch(void* const* d_in, const int* in_sizes, int n_in,
                              void* d_out, int out_size) {
    (void)in_sizes; (void)n_in; (void)out_size;
    const float* xi = (const float*)d_in[0];
    const float* xj = (const float*)d_in[1];

    cudaFuncSetAttribute(gemm_kernel,
                         cudaFuncAttributeMaxDynamicSharedMemorySize, SMEM_BYTES);

    prep_kernel<<<NTOT, 256>>>(xi, xj);
    gemm_kernel<<<GRID, 256, SMEM_BYTES>>>();
    final_kernel<<<1, 256>>>((float*)d_out);
}

// round 3
// speedup vs baseline: 1.5745x; 1.5745x over previous
#include <cuda_runtime.h>
#include <cuda_bf16.h>
#include <cstdint>

#define DINL __device__ __forceinline__

// ---------------- problem constants ----------------
constexpr int   BHALF = 4096;
constexpr int   NTOT  = 8192;           // 2B rows
constexpr int   DDIM  = 256;            // K
constexpr int   TILE  = 128;            // M = N tile
constexpr int   RBLK  = NTOT / TILE;    // 64 row/col blocks
constexpr int   NTRI  = RBLK * (RBLK + 1) / 2;   // 2080 triangle tiles
constexpr int   GRID  = 148;            // one exact wave
// alpha = sqrt(log2(e)/T): (a u_i)·(a u_j) = s·log2(e)/T = y, so exp(s/T)=2^y
constexpr float ALPHA = 1.6986436f;
constexpr float LN2F  = 0.693147180559945f;

// SMEM: A tile (64KB) + two B buffers (64KB) + column-reduce scratch
constexpr int SM_A    = 0;
constexpr int SM_B0   = 65536;
constexpr int SM_B1   = 131072;
constexpr int SM_COLS = 196608;                 // 8 warps * 136 floats
constexpr int SMEM_BYTES = 196608 + 8 * 136 * 4;  // 200960

// ---------------- device scratch (no allocation allowed) --------------------
__device__ __align__(16) __nv_bfloat16 g_z[NTOT * DDIM];   // 4 MB
__device__ float g_partial[NTOT];
__device__ float g_pos[NTOT];

// ---------------- PTX helpers ----------------
DINL uint32_t smem_u32(const void* p) {
    uint32_t a;
    asm("{ .reg .u64 t; cvta.to.shared.u64 t, %1; cvt.u32.u64 %0, t; }"
        : "=r"(a) : "l"(p));
    return a;
}
DINL float ex2f(float x) { float r; asm("ex2.approx.f32 %0, %1;" : "=f"(r) : "f"(x)); return r; }
DINL float lg2f(float x) { float r; asm("lg2.approx.f32 %0, %1;" : "=f"(r) : "f"(x)); return r; }

DINL void cp_commit() { asm volatile("cp.async.commit_group;" ::: "memory"); }
DINL void cp_wait0()  { asm volatile("cp.async.wait_group 0;" ::: "memory"); }

DINL void ldsm4(uint32_t& d0, uint32_t& d1, uint32_t& d2, uint32_t& d3, uint32_t addr) {
    asm volatile("ldmatrix.sync.aligned.m8n8.x4.shared.b16 {%0,%1,%2,%3}, [%4];"
                 : "=r"(d0), "=r"(d1), "=r"(d2), "=r"(d3) : "r"(addr));
}
DINL void mma16816(float* c, uint32_t a0, uint32_t a1, uint32_t a2, uint32_t a3,
                   uint32_t b0, uint32_t b1) {
    asm volatile("mma.sync.aligned.m16n8k16.row.col.f32.bf16.bf16.f32 "
                 "{%0,%1,%2,%3}, {%4,%5,%6,%7}, {%8,%9}, {%0,%1,%2,%3};"
                 : "+f"(c[0]), "+f"(c[1]), "+f"(c[2]), "+f"(c[3])
                 : "r"(a0), "r"(a1), "r"(a2), "r"(a3), "r"(b0), "r"(b1));
}

// Load one 128x256 bf16 tile of g_z into SMEM, XOR-swizzled (16B chunk index
// within 512B row XORed with row&7 -> conflict-free ldmatrix).
DINL void load_tile(uint32_t dst, int row0) {
    const char* src = reinterpret_cast<const char*>(g_z) + (size_t)row0 * 512;
    const int t = threadIdx.x;
    #pragma unroll
    for (int it = 0; it < 16; ++it) {
        int lin = it * 256 + t;
        int row = lin >> 5;
        int ch  = lin & 31;
        uint32_t sw = (uint32_t)row * 512u + (uint32_t)((ch ^ (row & 7)) << 4);
        const void* gp = src + (size_t)row * 512 + (size_t)ch * 16;
        asm volatile("cp.async.cg.shared.global [%0], [%1], 16;"
                     :: "r"(dst + sw), "l"(gp) : "memory");
    }
}

// ---------------- fused per-tile compute: 128x128 mma + exp2 + sums ---------
// Row sums accumulate into ra0/ra1 (registers). For off-diagonal tiles,
// per-thread column partials (32, over this thread's 2 rows) land in colp.
DINL void compute_tile(uint32_t a_base, uint32_t b_base, int w, int lane,
                       bool diag, bool pos, int ib, int jb,
                       float& ra0, float& ra1, float* colp) {
    const int mi = lane >> 3, li = lane & 7;
    const int rA = w * 16 + ((mi & 1) << 3) + li;
    const uint32_t aRow = a_base + (uint32_t)rA * 512u;
    const int axr = rA & 7, acp = mi >> 1;
    const int rBo = ((mi >> 1) << 3) + li;
    const int bcp = mi & 1;

    float acc[16][4];
    #pragma unroll
    for (int j = 0; j < 16; ++j) {
        acc[j][0] = 0.f; acc[j][1] = 0.f; acc[j][2] = 0.f; acc[j][3] = 0.f;
    }

    #pragma unroll 4
    for (int s = 0; s < 16; ++s) {
        uint32_t a0, a1, a2, a3;
        ldsm4(a0, a1, a2, a3, aRow + (uint32_t)(((s * 2 + acp) ^ axr) << 4));
        #pragma unroll
        for (int jp = 0; jp < 8; ++jp) {
            int r = jp * 16 + rBo;
            uint32_t b0, b1, b2, b3;
            ldsm4(b0, b1, b2, b3,
                  b_base + (uint32_t)r * 512u +
                  (uint32_t)(((s * 2 + bcp) ^ (r & 7)) << 4));
            mma16816(acc[2 * jp],     a0, a1, a2, a3, b0, b1);
            mma16816(acc[2 * jp + 1], a0, a1, a2, a3, b2, b3);
        }
    }

    const int baseRow = w * 16 + (lane >> 2);   // rows baseRow, baseRow+8
    const int baseCol = (lane & 3) * 2;

    if (diag) {
        #pragma unroll
        for (int j = 0; j < 16; ++j) {
            #pragma unroll
            for (int q = 0; q < 4; ++q) {
                int rl = baseRow + ((q & 2) << 2);
                int cl = j * 8 + baseCol + (q & 1);
                float e = ex2f(acc[j][q]);
                if (rl == cl) e = 0.f;                    // mask self-sim
                if (q & 2) ra1 += e; else ra0 += e;
            }
        }
    } else {
        #pragma unroll
        for (int k = 0; k < 32; ++k) colp[k] = 0.f;
        #pragma unroll
        for (int j = 0; j < 16; ++j) {
            float e0 = ex2f(acc[j][0]);
            float e1 = ex2f(acc[j][1]);
            float e2 = ex2f(acc[j][2]);
            float e3 = ex2f(acc[j][3]);
            if (pos) {
                int cl0 = j * 8 + baseCol;
                if (cl0     == baseRow)     { g_pos[ib*128+baseRow]   = acc[j][0]; g_pos[jb*128+baseRow]   = acc[j][0]; }
                if (cl0 + 1 == baseRow)     { g_pos[ib*128+baseRow]   = acc[j][1]; g_pos[jb*128+baseRow]   = acc[j][1]; }
                if (cl0     == baseRow + 8) { g_pos[ib*128+baseRow+8] = acc[j][2]; g_pos[jb*128+baseRow+8] = acc[j][2]; }
                if (cl0 + 1 == baseRow + 8) { g_pos[ib*128+baseRow+8] = acc[j][3]; g_pos[jb*128+baseRow+8] = acc[j][3]; }
            }
            ra0 += e0 + e1;
            ra1 += e2 + e3;
            colp[j * 2]     += e0 + e2;   // col j*8 + baseCol
            colp[j * 2 + 1] += e1 + e3;   // col j*8 + baseCol + 1
        }
    }
}

DINL void flush_rows(int rb, int w, int lane, float& a0, float& a1) {
    float v0 = a0, v1 = a1;
    v0 += __shfl_xor_sync(0xffffffffu, v0, 1);
    v0 += __shfl_xor_sync(0xffffffffu, v0, 2);
    v1 += __shfl_xor_sync(0xffffffffu, v1, 1);
    v1 += __shfl_xor_sync(0xffffffffu, v1, 2);
    if ((lane & 3) == 0) {
        int r = rb * 128 + w * 16 + (lane >> 2);
        atomicAdd(&g_partial[r],     v0);
        atomicAdd(&g_partial[r + 8], v1);
    }
    a0 = 0.f; a1 = 0.f;
}

// decode (v,k) -> (i,j): virtual row v pairs strip v (64-v tiles) with
// strip 63-v (v+1 tiles): constant 65 tiles per virtual row.
DINL void vk2ij(int v, int k, int& i, int& j) {
    int L = 64 - v;
    if (k < L) { i = v; j = v + k; }
    else       { i = 63 - v; j = i + (k - L); }
}

// ---------------- kernel 1: normalize + pre-scale + bf16 cast ----------------
__global__ void prep_kernel(const float* __restrict__ xi, const float* __restrict__ xj) {
    const int wid = threadIdx.x >> 5, lane = threadIdx.x & 31;
    const int row = blockIdx.x * 8 + wid;
    const float* x = (row < BHALF) ? (xi + (size_t)row * DDIM)
                                   : (xj + (size_t)(row - BHALF) * DDIM);
    float4 v0 = *reinterpret_cast<const float4*>(x + lane * 8);
    float4 v1 = *reinterpret_cast<const float4*>(x + lane * 8 + 4);
    float s = v0.x*v0.x + v0.y*v0.y + v0.z*v0.z + v0.w*v0.w
            + v1.x*v1.x + v1.y*v1.y + v1.z*v1.z + v1.w*v1.w;
    #pragma unroll
    for (int o = 16; o; o >>= 1) s += __shfl_xor_sync(0xffffffffu, s, o);
    float scale = ALPHA / fmaxf(sqrtf(s), 1e-12f);
    __nv_bfloat162 h0 = __floats2bfloat162_rn(v0.x*scale, v0.y*scale);
    __nv_bfloat162 h1 = __floats2bfloat162_rn(v0.z*scale, v0.w*scale);
    __nv_bfloat162 h2 = __floats2bfloat162_rn(v1.x*scale, v1.y*scale);
    __nv_bfloat162 h3 = __floats2bfloat162_rn(v1.z*scale, v1.w*scale);
    uint4 pk;
    pk.x = *reinterpret_cast<uint32_t*>(&h0);
    pk.y = *reinterpret_cast<uint32_t*>(&h1);
    pk.z = *reinterpret_cast<uint32_t*>(&h2);
    pk.w = *reinterpret_cast<uint32_t*>(&h3);
    *reinterpret_cast<uint4*>(&g_z[(size_t)row * DDIM + lane * 8]) = pk;
    if (lane == 0) g_partial[row] = 0.f;   // zero accumulators every launch
}

// ---------------- kernel 2: triangle-only fused GEMM ------------------------
__global__ void __launch_bounds__(256, 1) gemm_kernel() {
    extern __shared__ char smem[];
    const uint32_t sb = smem_u32(smem);
    const uint32_t A  = sb + SM_A;
    const uint32_t B0 = sb + SM_B0;
    const uint32_t B1 = sb + SM_B1;
    float* smem_cols = reinterpret_cast<float*>(smem + SM_COLS);
    const int tid = threadIdx.x, w = tid >> 5, lane = tid & 31;

    // contiguous range over 2080 triangle tiles: 2080 = 148*14 + 8
    const int c = blockIdx.x;
    const int start = c * 14 + min(c, 8);
    const int count = 14 + (c < 8 ? 1 : 0);

    int v = start / 65, k = start % 65;
    int i, j; vk2ij(v, k, i, j);

    load_tile(A, i * 128);
    load_tile(B0, j * 128);
    cp_commit();
    cp_wait0();
    __syncthreads();

    float ra0 = 0.f, ra1 = 0.f;
    float colp[32];
    int buf = 0;

    for (int n = 0; n < count; ++n) {
        const bool haveNext = (n + 1 < count);
        int nv = v, nk = k + 1;
        if (nk == 65) { nv = v + 1; nk = 0; }
        int ni = 0, nj = 0;
        if (haveNext) vk2ij(nv, nk, ni, nj);

        // prefetch next B into the alternate buffer (overlaps compute)
        if (haveNext) { load_tile(buf ? B0 : B1, nj * 128); cp_commit(); }

        const bool diag = (i == j);
        compute_tile(A, buf ? B1 : B0, w, lane,
                     diag, j == i + 32, i, j, ra0, ra1, colp);

        // column reduce-scatter: 32 -> 4 values per thread over 8-lane groups
        if (!diag) {
            int base16 = 0;
            {
                bool hi = (lane >> 2) & 1;
                #pragma unroll
                for (int t = 0; t < 16; ++t) {
                    float send = hi ? colp[t] : colp[t + 16];
                    float r = __shfl_xor_sync(0xffffffffu, send, 4);
                    colp[t] = (hi ? colp[t + 16] : colp[t]) + r;
                }
                base16 += hi ? 16 : 0;
            }
            {
                bool hi = (lane >> 3) & 1;
                #pragma unroll
                for (int t = 0; t < 8; ++t) {
                    float send = hi ? colp[t] : colp[t + 8];
                    float r = __shfl_xor_sync(0xffffffffu, send, 8);
                    colp[t] = (hi ? colp[t + 8] : colp[t]) + r;
                }
                base16 += hi ? 8 : 0;
            }
            {
                bool hi = (lane >> 4) & 1;
                #pragma unroll
                for (int t = 0; t < 4; ++t) {
                    float send = hi ? colp[t] : colp[t + 4];
                    float r = __shfl_xor_sync(0xffffffffu, send, 16);
                    colp[t] = (hi ? colp[t + 4] : colp[t]) + r;
                }
                base16 += hi ? 4 : 0;
            }
            const int m = lane & 3;
            #pragma unroll
            for (int t = 0; t < 4; ++t) {
                int c16 = base16 + t;
                int col = ((c16 >> 1) << 3) + 2 * m + (c16 & 1);
                smem_cols[w * 136 + col + (col >> 4)] = colp[t];
            }
        }
        __syncthreads();
        if (!diag && tid < 128) {
            const int col = tid + (tid >> 4);
            float s = 0.f;
            #pragma unroll
            for (int w8 = 0; w8 < 8; ++w8) s += smem_cols[w8 * 136 + col];
            atomicAdd(&g_partial[j * 128 + tid], s);
        }

        if (!haveNext || ni != i) flush_rows(i, w, lane, ra0, ra1);

        if (haveNext) {
            if (ni != i) { load_tile(A, ni * 128); cp_commit(); }
            cp_wait0();
            __syncthreads();
        }
        v = nv; k = nk; i = ni; j = nj;
        buf ^= 1;
    }
}

// ---------------- kernel 3: per-row log + positive term + mean ---------------
__global__ void final_kernel(float* __restrict__ out) {
    float local = 0.f;
    for (int r = threadIdx.x; r < NTOT; r += 1024) {
        // loss_r = ln(denom) - s_pos/T = ln2 * (log2(denom) - y_pos)
        local += lg2f(g_partial[r]) - g_pos[r];
    }
    #pragma unroll
    for (int o = 16; o; o >>= 1) local += __shfl_xor_sync(0xffffffffu, local, o);
    __shared__ float ws[32];
    if ((threadIdx.x & 31) == 0) ws[threadIdx.x >> 5] = local;
    __syncthreads();
    if (threadIdx.x < 32) {
        float t = ws[threadIdx.x];
        #pragma unroll
        for (int o = 16; o; o >>= 1) t += __shfl_xor_sync(0xffffffffu, t, o);
        if (threadIdx.x == 0) out[0] = t * (LN2F / (float)NTOT);
    }
}

// ---------------- entry point ----------------
extern "C" void kernel_launch(void* const* d_in, const int* in_sizes, int n_in,
                              void* d_out, int out_size) {
    (void)in_sizes; (void)n_in; (void)out_size;
    const float* xi = (const float*)d_in[0];
    const float* xj = (const float*)d_in[1];

    cudaFuncSetAttribute(gemm_kernel,
                         cudaFuncAttributeMaxDynamicSharedMemorySize, SMEM_BYTES);

    prep_kernel<<<NTOT / 8, 256>>>(xi, xj);
    gemm_kernel<<<GRID, 256, SMEM_BYTES>>>();
    final_kernel<<<1, 1024>>>((float*)d_out);
}